// round 1
// baseline (speedup 1.0000x reference)
#include <cuda_runtime.h>
#include <cuda_bf16.h>

#define N_NODES  100000
#define N_EDGES  3200000
#define N_GRAPHS 512
#define HID      16
#define LABELS   10
#define POOL_CHUNK 8

// ---------------- scratch (device globals: no allocs allowed) ----------------
__device__ float g_deg [N_NODES];
__device__ float g_dinv[N_NODES];
__device__ float g_hws [N_NODES * HID];   // dinv-scaled features (edge-kernel source)
__device__ float g_acc [N_NODES * HID];   // segment-sum accumulator (edge-kernel dest)
__device__ float g_gsum[N_GRAPHS * HID];
__device__ float g_gcnt[N_GRAPHS];

// vectorized fp32 reduction (sm_90+): 1 instruction instead of 4 atomicAdds
__device__ __forceinline__ void red_add_v4(float* addr, float4 v) {
    asm volatile("red.global.add.v4.f32 [%0], {%1,%2,%3,%4};"
                 :: "l"(addr), "f"(v.x), "f"(v.y), "f"(v.z), "f"(v.w)
                 : "memory");
}

// ---------------- K0: init degree (=1 covers self-loop) + zero pool buffers --
__global__ void k_init() {
    int i = blockIdx.x * blockDim.x + threadIdx.x;
    if (i < N_NODES)        g_deg[i]  = 1.0f;
    if (i < N_GRAPHS * HID) g_gsum[i] = 0.0f;
    if (i < N_GRAPHS)       g_gcnt[i] = 0.0f;
}

// ---------------- K1: degree from dst -----------------------------------------
__global__ void k_degree(const int* __restrict__ dst) {
    int e = blockIdx.x * blockDim.x + threadIdx.x;
    if (e < N_EDGES) atomicAdd(&g_deg[dst[e]], 1.0f);   // compiles to RED
}

// ---------------- K2: dinv, embed, h0@W1, scale, seed acc (self-loop) --------
__global__ void k_node1(const int* __restrict__ x, const float* __restrict__ emb,
                        const float* __restrict__ W1) {
    __shared__ float sW[HID * HID];
    if (threadIdx.x < HID * HID) sW[threadIdx.x] = W1[threadIdx.x];
    __syncthreads();
    int i = blockIdx.x * blockDim.x + threadIdx.x;
    if (i >= N_NODES) return;

    float dv = rsqrtf(g_deg[i]);          // deg >= 1 always (self-loop)
    g_dinv[i] = dv;

    int xi = x[i];
    float h0[HID];
    const float4* ep = (const float4*)(emb + (size_t)xi * HID);
#pragma unroll
    for (int q = 0; q < 4; q++) {
        float4 v = __ldg(ep + q);
        h0[4*q+0] = v.x; h0[4*q+1] = v.y; h0[4*q+2] = v.z; h0[4*q+3] = v.w;
    }
    float hw[HID];
#pragma unroll
    for (int j = 0; j < HID; j++) {
        float s = 0.0f;
#pragma unroll
        for (int k = 0; k < HID; k++) s = fmaf(h0[k], sW[k*HID + j], s);
        hw[j] = s * dv;                   // pre-scale by dinv[src]
    }
    float4* o1 = (float4*)(g_hws + (size_t)i * HID);
    float4* o2 = (float4*)(g_acc + (size_t)i * HID);
#pragma unroll
    for (int q = 0; q < 4; q++) {
        float4 v = make_float4(hw[4*q], hw[4*q+1], hw[4*q+2], hw[4*q+3]);
        o1[q] = v; o2[q] = v;             // acc seeded with self-loop term
    }
}

// ---------------- K3/K5: edge scatter acc[dst] += hws[src] -------------------
__global__ void k_edge(const int* __restrict__ src, const int* __restrict__ dst) {
    int e = blockIdx.x * blockDim.x + threadIdx.x;
    if (e >= N_EDGES) return;
    int s = src[e];
    int d = dst[e];
    const float4* hp = (const float4*)(g_hws + (size_t)s * HID);
    float4 a = __ldg(hp + 0);
    float4 b = __ldg(hp + 1);
    float4 c = __ldg(hp + 2);
    float4 f = __ldg(hp + 3);
    float* op = g_acc + (size_t)d * HID;
    red_add_v4(op + 0,  a);
    red_add_v4(op + 4,  b);
    red_add_v4(op + 8,  c);
    red_add_v4(op + 12, f);
}

// ---------------- K4: h1 = relu(dinv*acc + b1); h1@W2; scale; re-seed acc ----
__global__ void k_node2(const float* __restrict__ W2, const float* __restrict__ b1) {
    __shared__ float sW[HID * HID];
    __shared__ float sb[HID];
    if (threadIdx.x < HID * HID) sW[threadIdx.x] = W2[threadIdx.x];
    if (threadIdx.x < HID)       sb[threadIdx.x] = b1[threadIdx.x];
    __syncthreads();
    int i = blockIdx.x * blockDim.x + threadIdx.x;
    if (i >= N_NODES) return;

    float dv = g_dinv[i];
    float h1[HID];
    const float4* ap = (const float4*)(g_acc + (size_t)i * HID);
#pragma unroll
    for (int q = 0; q < 4; q++) {
        float4 v = ap[q];
        h1[4*q+0] = fmaxf(fmaf(dv, v.x, sb[4*q+0]), 0.0f);
        h1[4*q+1] = fmaxf(fmaf(dv, v.y, sb[4*q+1]), 0.0f);
        h1[4*q+2] = fmaxf(fmaf(dv, v.z, sb[4*q+2]), 0.0f);
        h1[4*q+3] = fmaxf(fmaf(dv, v.w, sb[4*q+3]), 0.0f);
    }
    float hw[HID];
#pragma unroll
    for (int j = 0; j < HID; j++) {
        float s = 0.0f;
#pragma unroll
        for (int k = 0; k < HID; k++) s = fmaf(h1[k], sW[k*HID + j], s);
        hw[j] = s * dv;
    }
    float4* o1 = (float4*)(g_hws + (size_t)i * HID);
    float4* o2 = (float4*)(g_acc + (size_t)i * HID);
#pragma unroll
    for (int q = 0; q < 4; q++) {
        float4 v = make_float4(hw[4*q], hw[4*q+1], hw[4*q+2], hw[4*q+3]);
        o1[q] = v; o2[q] = v;
    }
}

// ---------------- K6: h2 = relu(dinv*acc + b2); mean-pool (run-aggregated) ---
__global__ void k_pool(const int* __restrict__ batch, const float* __restrict__ b2) {
    int t = blockIdx.x * blockDim.x + threadIdx.x;
    int start = t * POOL_CHUNK;
    if (start >= N_NODES) return;
    int end = min(start + POOL_CHUNK, N_NODES);

    float sb[HID];
#pragma unroll
    for (int j = 0; j < HID; j++) sb[j] = __ldg(b2 + j);

    float lacc[HID];
#pragma unroll
    for (int j = 0; j < HID; j++) lacc[j] = 0.0f;
    float lcnt = 0.0f;
    int cur = __ldg(batch + start);

    for (int i = start; i < end; i++) {
        int bg = __ldg(batch + i);
        if (bg != cur) {
            float* gp = g_gsum + (size_t)cur * HID;
#pragma unroll
            for (int q = 0; q < 4; q++)
                red_add_v4(gp + 4*q, make_float4(lacc[4*q], lacc[4*q+1], lacc[4*q+2], lacc[4*q+3]));
            atomicAdd(&g_gcnt[cur], lcnt);
#pragma unroll
            for (int j = 0; j < HID; j++) lacc[j] = 0.0f;
            lcnt = 0.0f;
            cur = bg;
        }
        float dv = g_dinv[i];
        const float4* ap = (const float4*)(g_acc + (size_t)i * HID);
#pragma unroll
        for (int q = 0; q < 4; q++) {
            float4 v = ap[q];
            lacc[4*q+0] += fmaxf(fmaf(dv, v.x, sb[4*q+0]), 0.0f);
            lacc[4*q+1] += fmaxf(fmaf(dv, v.y, sb[4*q+1]), 0.0f);
            lacc[4*q+2] += fmaxf(fmaf(dv, v.z, sb[4*q+2]), 0.0f);
            lacc[4*q+3] += fmaxf(fmaf(dv, v.w, sb[4*q+3]), 0.0f);
        }
        lcnt += 1.0f;
    }
    // final flush
    float* gp = g_gsum + (size_t)cur * HID;
#pragma unroll
    for (int q = 0; q < 4; q++)
        red_add_v4(gp + 4*q, make_float4(lacc[4*q], lacc[4*q+1], lacc[4*q+2], lacc[4*q+3]));
    atomicAdd(&g_gcnt[cur], lcnt);
}

// ---------------- K7: classifier head ----------------------------------------
__global__ void k_out(const float* __restrict__ Wc, const float* __restrict__ bc,
                      float* __restrict__ out) {
    __shared__ float sW[HID * LABELS];
    __shared__ float sb[LABELS];
    if (threadIdx.x < HID * LABELS) sW[threadIdx.x] = Wc[threadIdx.x];
    if (threadIdx.x < LABELS)       sb[threadIdx.x] = bc[threadIdx.x];
    __syncthreads();
    int g = blockIdx.x * blockDim.x + threadIdx.x;
    if (g >= N_GRAPHS) return;

    float inv = 1.0f / fmaxf(g_gcnt[g], 1.0f);
    float p[HID];
#pragma unroll
    for (int k = 0; k < HID; k++) p[k] = g_gsum[(size_t)g * HID + k] * inv;
#pragma unroll
    for (int l = 0; l < LABELS; l++) {
        float s = sb[l];
#pragma unroll
        for (int k = 0; k < HID; k++) s = fmaf(p[k], sW[k*LABELS + l], s);
        out[(size_t)g * LABELS + l] = s;
    }
}

// ---------------- launch ------------------------------------------------------
extern "C" void kernel_launch(void* const* d_in, const int* in_sizes, int n_in,
                              void* d_out, int out_size) {
    const int*   x     = (const int*)  d_in[0];
    const int*   ei    = (const int*)  d_in[1];
    const int*   batch = (const int*)  d_in[2];
    const float* emb   = (const float*)d_in[3];
    const float* W1    = (const float*)d_in[4];
    const float* b1    = (const float*)d_in[5];
    const float* W2    = (const float*)d_in[6];
    const float* b2    = (const float*)d_in[7];
    const float* Wc    = (const float*)d_in[8];
    const float* bc    = (const float*)d_in[9];
    float* out = (float*)d_out;

    const int* src = ei;             // edge_index[0]
    const int* dst = ei + N_EDGES;   // edge_index[1]

    const int TB = 256;
    k_init  <<<(N_NODES + TB - 1) / TB, TB>>>();
    k_degree<<<(N_EDGES + TB - 1) / TB, TB>>>(dst);
    k_node1 <<<(N_NODES + TB - 1) / TB, TB>>>(x, emb, W1);
    k_edge  <<<(N_EDGES + TB - 1) / TB, TB>>>(src, dst);
    k_node2 <<<(N_NODES + TB - 1) / TB, TB>>>(W2, b1);
    k_edge  <<<(N_EDGES + TB - 1) / TB, TB>>>(src, dst);
    int pool_threads = (N_NODES + POOL_CHUNK - 1) / POOL_CHUNK;
    k_pool  <<<(pool_threads + TB - 1) / TB, TB>>>(batch, b2);
    k_out   <<<(N_GRAPHS + TB - 1) / TB, TB>>>(Wc, bc, out);
}

// round 2
// speedup vs baseline: 1.4698x; 1.4698x over previous
#include <cuda_runtime.h>
#include <cuda_bf16.h>

#define N_NODES  100000
#define N_EDGES  3200000
#define N_GRAPHS 512
#define HID      16
#define LABELS   10
#define POOL_CHUNK 8

#define SCAN_TB   1024
#define SCAN_NBLK ((N_NODES + SCAN_TB - 1) / SCAN_TB)   // 98

// ---------------- scratch (device globals: no allocs allowed) ----------------
__device__ int   g_cnt   [N_NODES];          // in-degree (w/o self loop)
__device__ float g_dinv  [N_NODES];
__device__ int   g_rowptr[N_NODES + 1];      // CSR row offsets (by dst)
__device__ int   g_cursor[N_NODES];          // fill cursors
__device__ int   g_csr   [N_EDGES];          // CSR column = src node
__device__ int   g_blk   [SCAN_NBLK];        // scan block sums
__device__ int   g_blkoff[SCAN_NBLK];        // scanned block offsets
__device__ float g_hws   [N_NODES * HID];    // dinv-scaled features (gather source)
__device__ float g_acc   [N_NODES * HID];    // aggregation result
__device__ float g_gsum  [N_GRAPHS * HID];
__device__ float g_gcnt  [N_GRAPHS];

__device__ __forceinline__ void red_add_v4(float* addr, float4 v) {
    asm volatile("red.global.add.v4.f32 [%0], {%1,%2,%3,%4};"
                 :: "l"(addr), "f"(v.x), "f"(v.y), "f"(v.z), "f"(v.w)
                 : "memory");
}

// ---------------- K0: zero counters/pool buffers ------------------------------
__global__ void k_init() {
    int i = blockIdx.x * blockDim.x + threadIdx.x;
    if (i < N_NODES)        g_cnt[i]  = 0;
    if (i < N_GRAPHS * HID) g_gsum[i] = 0.0f;
    if (i < N_GRAPHS)       g_gcnt[i] = 0.0f;
}

// ---------------- K1: degree histogram over dst (4 edges/thread, int4 loads) -
__global__ void k_degree(const int* __restrict__ dst) {
    int t = blockIdx.x * blockDim.x + threadIdx.x;
    int e = t * 4;
    if (e + 3 < N_EDGES) {
        int4 d = __ldg((const int4*)(dst + e));
        atomicAdd(&g_cnt[d.x], 1);
        atomicAdd(&g_cnt[d.y], 1);
        atomicAdd(&g_cnt[d.z], 1);
        atomicAdd(&g_cnt[d.w], 1);
    } else {
        for (int k = e; k < N_EDGES; k++) atomicAdd(&g_cnt[__ldg(dst + k)], 1);
    }
}

// ---------------- K2a: per-block exclusive scan of g_cnt ---------------------
__global__ void k_scan1() {
    __shared__ int s[SCAN_TB];
    int i = blockIdx.x * SCAN_TB + threadIdx.x;
    int v = (i < N_NODES) ? g_cnt[i] : 0;
    s[threadIdx.x] = v;
    __syncthreads();
#pragma unroll
    for (int off = 1; off < SCAN_TB; off <<= 1) {
        int t = (threadIdx.x >= off) ? s[threadIdx.x - off] : 0;
        __syncthreads();
        s[threadIdx.x] += t;
        __syncthreads();
    }
    if (i < N_NODES) g_rowptr[i] = s[threadIdx.x] - v;     // exclusive within block
    if (threadIdx.x == SCAN_TB - 1) g_blk[blockIdx.x] = s[SCAN_TB - 1];
}

// ---------------- K2b: scan block sums (tiny, 1 thread) ----------------------
__global__ void k_scan2() {
    if (threadIdx.x == 0 && blockIdx.x == 0) {
        int run = 0;
        for (int b = 0; b < SCAN_NBLK; b++) { g_blkoff[b] = run; run += g_blk[b]; }
    }
}

// ---------------- K2c: add block offsets, init cursor, cap rowptr ------------
__global__ void k_scan3() {
    int i = blockIdx.x * blockDim.x + threadIdx.x;
    if (i < N_NODES) {
        int r = g_rowptr[i] + g_blkoff[i / SCAN_TB];
        g_rowptr[i] = r;
        g_cursor[i] = r;
    }
    if (i == 0) g_rowptr[N_NODES] = N_EDGES;
}

// ---------------- K3: CSR fill (4 edges/thread) ------------------------------
__global__ void k_fill(const int* __restrict__ src, const int* __restrict__ dst) {
    int t = blockIdx.x * blockDim.x + threadIdx.x;
    int e = t * 4;
    if (e + 3 < N_EDGES) {
        int4 s = __ldg((const int4*)(src + e));
        int4 d = __ldg((const int4*)(dst + e));
        g_csr[atomicAdd(&g_cursor[d.x], 1)] = s.x;
        g_csr[atomicAdd(&g_cursor[d.y], 1)] = s.y;
        g_csr[atomicAdd(&g_cursor[d.z], 1)] = s.z;
        g_csr[atomicAdd(&g_cursor[d.w], 1)] = s.w;
    } else {
        for (int k = e; k < N_EDGES; k++)
            g_csr[atomicAdd(&g_cursor[__ldg(dst + k)], 1)] = __ldg(src + k);
    }
}

// ---------------- K4: dinv, embed, h0@W1, scale -> hws -----------------------
__global__ void k_node1(const int* __restrict__ x, const float* __restrict__ emb,
                        const float* __restrict__ W1) {
    __shared__ float sW[HID * HID];
    if (threadIdx.x < HID * HID) sW[threadIdx.x] = W1[threadIdx.x];
    __syncthreads();
    int i = blockIdx.x * blockDim.x + threadIdx.x;
    if (i >= N_NODES) return;

    float dv = rsqrtf((float)(g_cnt[i] + 1));    // +1 = self loop
    g_dinv[i] = dv;

    int xi = x[i];
    float h0[HID];
    const float4* ep = (const float4*)(emb + (size_t)xi * HID);
#pragma unroll
    for (int q = 0; q < 4; q++) {
        float4 v = __ldg(ep + q);
        h0[4*q+0] = v.x; h0[4*q+1] = v.y; h0[4*q+2] = v.z; h0[4*q+3] = v.w;
    }
    float4* o = (float4*)(g_hws + (size_t)i * HID);
#pragma unroll
    for (int q = 0; q < 4; q++) {
        float4 r;
        float* rp = (float*)&r;
#pragma unroll
        for (int jj = 0; jj < 4; jj++) {
            int j = 4*q + jj;
            float s = 0.0f;
#pragma unroll
            for (int k = 0; k < HID; k++) s = fmaf(h0[k], sW[k*HID + j], s);
            rp[jj] = s * dv;
        }
        o[q] = r;
    }
}

// ---------------- K5/K7: warp-per-node CSR gather: acc[i] = Σ hws[nbr] + hws[i]
__global__ void k_gather() {
    int warp = (blockIdx.x * blockDim.x + threadIdx.x) >> 5;
    if (warp >= N_NODES) return;
    int lane = threadIdx.x & 31;
    int q = lane & 3;                 // quarter of feature row (float4)
    int beg = __ldg(&g_rowptr[warp]);
    int end = __ldg(&g_rowptr[warp + 1]);

    float4 acc = make_float4(0.f, 0.f, 0.f, 0.f);
    for (int p = beg + (lane >> 2); p < end; p += 8) {
        int s = __ldg(&g_csr[p]);
        float4 v = __ldg((const float4*)(g_hws + (size_t)s * HID) + q);
        acc.x += v.x; acc.y += v.y; acc.z += v.z; acc.w += v.w;
    }
    // reduce the 8 neighbor slots (lane stride 4)
#pragma unroll
    for (int off = 4; off < 32; off <<= 1) {
        acc.x += __shfl_xor_sync(0xffffffffu, acc.x, off);
        acc.y += __shfl_xor_sync(0xffffffffu, acc.y, off);
        acc.z += __shfl_xor_sync(0xffffffffu, acc.z, off);
        acc.w += __shfl_xor_sync(0xffffffffu, acc.w, off);
    }
    if (lane < 4) {                   // lane == q here
        float4 self = __ldg((const float4*)(g_hws + (size_t)warp * HID) + lane);
        acc.x += self.x; acc.y += self.y; acc.z += self.z; acc.w += self.w;
        ((float4*)(g_acc + (size_t)warp * HID))[lane] = acc;
    }
}

// ---------------- K6: h1 = relu(dinv*acc + b1); h1@W2; scale -> hws ----------
__global__ void k_node2(const float* __restrict__ W2, const float* __restrict__ b1) {
    __shared__ float sW[HID * HID];
    __shared__ float sb[HID];
    if (threadIdx.x < HID * HID) sW[threadIdx.x] = W2[threadIdx.x];
    if (threadIdx.x < HID)       sb[threadIdx.x] = b1[threadIdx.x];
    __syncthreads();
    int i = blockIdx.x * blockDim.x + threadIdx.x;
    if (i >= N_NODES) return;

    float dv = g_dinv[i];
    float h1[HID];
    const float4* ap = (const float4*)(g_acc + (size_t)i * HID);
#pragma unroll
    for (int q = 0; q < 4; q++) {
        float4 v = ap[q];
        h1[4*q+0] = fmaxf(fmaf(dv, v.x, sb[4*q+0]), 0.0f);
        h1[4*q+1] = fmaxf(fmaf(dv, v.y, sb[4*q+1]), 0.0f);
        h1[4*q+2] = fmaxf(fmaf(dv, v.z, sb[4*q+2]), 0.0f);
        h1[4*q+3] = fmaxf(fmaf(dv, v.w, sb[4*q+3]), 0.0f);
    }
    float4* o = (float4*)(g_hws + (size_t)i * HID);
#pragma unroll
    for (int q = 0; q < 4; q++) {
        float4 r;
        float* rp = (float*)&r;
#pragma unroll
        for (int jj = 0; jj < 4; jj++) {
            int j = 4*q + jj;
            float s = 0.0f;
#pragma unroll
            for (int k = 0; k < HID; k++) s = fmaf(h1[k], sW[k*HID + j], s);
            rp[jj] = s * dv;
        }
        o[q] = r;
    }
}

// ---------------- K8: h2 = relu(dinv*acc + b2); mean-pool (run-aggregated) ---
__global__ void k_pool(const int* __restrict__ batch, const float* __restrict__ b2) {
    int t = blockIdx.x * blockDim.x + threadIdx.x;
    int start = t * POOL_CHUNK;
    if (start >= N_NODES) return;
    int end = min(start + POOL_CHUNK, N_NODES);

    float sb[HID];
#pragma unroll
    for (int j = 0; j < HID; j++) sb[j] = __ldg(b2 + j);

    float lacc[HID];
#pragma unroll
    for (int j = 0; j < HID; j++) lacc[j] = 0.0f;
    float lcnt = 0.0f;
    int cur = __ldg(batch + start);

    for (int i = start; i < end; i++) {
        int bg = __ldg(batch + i);
        if (bg != cur) {
            float* gp = g_gsum + (size_t)cur * HID;
#pragma unroll
            for (int q = 0; q < 4; q++)
                red_add_v4(gp + 4*q, make_float4(lacc[4*q], lacc[4*q+1], lacc[4*q+2], lacc[4*q+3]));
            atomicAdd(&g_gcnt[cur], lcnt);
#pragma unroll
            for (int j = 0; j < HID; j++) lacc[j] = 0.0f;
            lcnt = 0.0f;
            cur = bg;
        }
        float dv = g_dinv[i];
        const float4* ap = (const float4*)(g_acc + (size_t)i * HID);
#pragma unroll
        for (int q = 0; q < 4; q++) {
            float4 v = ap[q];
            lacc[4*q+0] += fmaxf(fmaf(dv, v.x, sb[4*q+0]), 0.0f);
            lacc[4*q+1] += fmaxf(fmaf(dv, v.y, sb[4*q+1]), 0.0f);
            lacc[4*q+2] += fmaxf(fmaf(dv, v.z, sb[4*q+2]), 0.0f);
            lacc[4*q+3] += fmaxf(fmaf(dv, v.w, sb[4*q+3]), 0.0f);
        }
        lcnt += 1.0f;
    }
    float* gp = g_gsum + (size_t)cur * HID;
#pragma unroll
    for (int q = 0; q < 4; q++)
        red_add_v4(gp + 4*q, make_float4(lacc[4*q], lacc[4*q+1], lacc[4*q+2], lacc[4*q+3]));
    atomicAdd(&g_gcnt[cur], lcnt);
}

// ---------------- K9: classifier head ----------------------------------------
__global__ void k_out(const float* __restrict__ Wc, const float* __restrict__ bc,
                      float* __restrict__ out) {
    __shared__ float sW[HID * LABELS];
    __shared__ float sb[LABELS];
    if (threadIdx.x < HID * LABELS) sW[threadIdx.x] = Wc[threadIdx.x];
    if (threadIdx.x < LABELS)       sb[threadIdx.x] = bc[threadIdx.x];
    __syncthreads();
    int g = blockIdx.x * blockDim.x + threadIdx.x;
    if (g >= N_GRAPHS) return;

    float inv = 1.0f / fmaxf(g_gcnt[g], 1.0f);
    float p[HID];
#pragma unroll
    for (int k = 0; k < HID; k++) p[k] = g_gsum[(size_t)g * HID + k] * inv;
#pragma unroll
    for (int l = 0; l < LABELS; l++) {
        float s = sb[l];
#pragma unroll
        for (int k = 0; k < HID; k++) s = fmaf(p[k], sW[k*LABELS + l], s);
        out[(size_t)g * LABELS + l] = s;
    }
}

// ---------------- launch ------------------------------------------------------
extern "C" void kernel_launch(void* const* d_in, const int* in_sizes, int n_in,
                              void* d_out, int out_size) {
    const int*   x     = (const int*)  d_in[0];
    const int*   ei    = (const int*)  d_in[1];
    const int*   batch = (const int*)  d_in[2];
    const float* emb   = (const float*)d_in[3];
    const float* W1    = (const float*)d_in[4];
    const float* b1    = (const float*)d_in[5];
    const float* W2    = (const float*)d_in[6];
    const float* b2    = (const float*)d_in[7];
    const float* Wc    = (const float*)d_in[8];
    const float* bc    = (const float*)d_in[9];
    float* out = (float*)d_out;

    const int* src = ei;             // edge_index[0]
    const int* dst = ei + N_EDGES;   // edge_index[1]

    const int TB = 256;
    int edge_t4 = (N_EDGES + 3) / 4;

    k_init  <<<(N_NODES + TB - 1) / TB, TB>>>();
    k_degree<<<(edge_t4 + TB - 1) / TB, TB>>>(dst);
    k_scan1 <<<SCAN_NBLK, SCAN_TB>>>();
    k_scan2 <<<1, 32>>>();
    k_scan3 <<<(N_NODES + TB - 1) / TB, TB>>>();
    k_fill  <<<(edge_t4 + TB - 1) / TB, TB>>>(src, dst);
    k_node1 <<<(N_NODES + TB - 1) / TB, TB>>>(x, emb, W1);

    int gather_blocks = (N_NODES * 32 + TB - 1) / TB;
    k_gather<<<gather_blocks, TB>>>();
    k_node2 <<<(N_NODES + TB - 1) / TB, TB>>>(W2, b1);
    k_gather<<<gather_blocks, TB>>>();

    int pool_threads = (N_NODES + POOL_CHUNK - 1) / POOL_CHUNK;
    k_pool  <<<(pool_threads + TB - 1) / TB, TB>>>(batch, b2);
    k_out   <<<(N_GRAPHS + TB - 1) / TB, TB>>>(Wc, bc, out);
}